// round 2
// baseline (speedup 1.0000x reference)
#include <cuda_runtime.h>

#define BB 8
#define TT 2048
#define DD 128
#define NH 4
#define HDIM 32
#define BQ 32          // queries per attention block
#define BK 64          // keys per smem tile
#define SSTR 129       // smem row stride for Q/K/V tiles (conflict-free frags)
#define PSTR 257       // smem row stride for prob tile
#define QK_SCALE 0.17677669529663687f   // 1/sqrt(32)

// ---- scratch (static device globals; no allocation allowed) ----
__device__ float g_q[(size_t)BB*TT*DD];   // pre-scaled Q
__device__ float g_k[(size_t)BB*TT*DD];
__device__ float g_v[(size_t)BB*TT*DD];
__device__ float g_ctx[(size_t)BB*TT*DD];

// =====================================================================
// Kernel A: fused hawkes-proj + packed QKV projection.
// block = 32 tokens, 128 threads (thread t owns output dim t).
// =====================================================================
__global__ __launch_bounds__(128) void qkv_kernel(
    const float* __restrict__ lob, const float* __restrict__ hawkes,
    const float* __restrict__ Wp, const float* __restrict__ bp,
    const float* __restrict__ Win, const float* __restrict__ binv)
{
    __shared__ float sx[32][DD];    // lob tile, later overwritten with h tile
    __shared__ float shk[32][HDIM];

    const int t = threadIdx.x;
    const size_t tb = (size_t)blockIdx.x * 32;

    for (int i = t; i < 32 * DD; i += 128)
        sx[i >> 7][i & 127] = lob[tb * DD + i];
    for (int i = t; i < 32 * HDIM; i += 128)
        shk[i >> 5][i & 31] = hawkes[tb * HDIM + i];
    __syncthreads();

    // ---- q = lob @ Win[0:128].T, pre-scaled ----
    float acc[32];
#pragma unroll
    for (int i = 0; i < 32; i++) acc[i] = 0.f;
    for (int jc = 0; jc < DD; jc += 16) {
        float w[16];
#pragma unroll
        for (int j = 0; j < 16; j++) w[j] = Win[t * DD + jc + j];
#pragma unroll
        for (int tok = 0; tok < 32; tok++) {
            float a = 0.f;
#pragma unroll
            for (int j = 0; j < 16; j++) a += w[j] * sx[tok][jc + j];
            acc[tok] += a;
        }
    }
    {
        const float bq = binv[t];
#pragma unroll
        for (int tok = 0; tok < 32; tok++)
            g_q[(tb + tok) * DD + t] = (acc[tok] + bq) * QK_SCALE;
    }

    // ---- h = hawkes @ Wp.T + bp  (held in regs, then overwrite sx) ----
    float hv[32];
    {
        float w[32];
#pragma unroll
        for (int j = 0; j < 32; j++) w[j] = Wp[t * HDIM + j];
        const float bh = bp[t];
#pragma unroll
        for (int tok = 0; tok < 32; tok++) {
            float a = bh;
#pragma unroll
            for (int j = 0; j < 32; j++) a += w[j] * shk[tok][j];
            hv[tok] = a;
        }
    }
    __syncthreads();   // all q-phase reads of sx done
#pragma unroll
    for (int tok = 0; tok < 32; tok++) sx[tok][t] = hv[tok];
    __syncthreads();

    // ---- k, v from h ----
    float acck[32], accv[32];
#pragma unroll
    for (int i = 0; i < 32; i++) { acck[i] = 0.f; accv[i] = 0.f; }
    for (int jc = 0; jc < DD; jc += 16) {
        float wk[16], wv[16];
#pragma unroll
        for (int j = 0; j < 16; j++) {
            wk[j] = Win[(DD + t) * DD + jc + j];
            wv[j] = Win[(2 * DD + t) * DD + jc + j];
        }
#pragma unroll
        for (int tok = 0; tok < 32; tok++) {
            float ak = 0.f, av = 0.f;
#pragma unroll
            for (int j = 0; j < 16; j++) {
                const float x = sx[tok][jc + j];
                ak += wk[j] * x;
                av += wv[j] * x;
            }
            acck[tok] += ak;
            accv[tok] += av;
        }
    }
    {
        const float bk = binv[DD + t];
        const float bv = binv[2 * DD + t];
#pragma unroll
        for (int tok = 0; tok < 32; tok++) {
            g_k[(tb + tok) * DD + t] = acck[tok] + bk;
            g_v[(tb + tok) * DD + t] = accv[tok] + bv;
        }
    }
}

// =====================================================================
// Kernel B: attention. block = (b, 32-query tile), 256 threads.
// Pass 1: softmax denominators (no max-subtraction; |s| <~ 2).
// Pass 2: recompute scores -> probs (smem) -> attn_w write + ctx GEMM.
// =====================================================================
__global__ __launch_bounds__(256, 2) void attn_kernel(float* __restrict__ attn_w)
{
    extern __shared__ float sm[];
    float* sQ  = sm;                    // BQ  x SSTR
    float* sKV = sQ + BQ * SSTR;        // BK  x SSTR
    float* sP  = sKV + BK * SSTR;       // BQ  x PSTR   (probs: [q][h*64+k])
    float* sL  = sP + BQ * PSTR;        // BQ * NH

    const int b   = blockIdx.y;
    const int q0  = blockIdx.x * BQ;
    const int tid = threadIdx.x;
    const int warp = tid >> 5, lane = tid & 31;

    const float* gq = g_q + ((size_t)b * TT + q0) * DD;
    const float* gk = g_k + (size_t)b * TT * DD;
    const float* gv = g_v + (size_t)b * TT * DD;

    for (int i = tid; i < BQ * DD; i += 256)
        sQ[(i >> 7) * SSTR + (i & 127)] = gq[i];
    if (tid < BQ * NH) sL[tid] = 0.f;
    __syncthreads();

    // score-phase mapping: warp -> (head, key-half); lane -> (qg, kg)
    const int h  = warp >> 1;
    const int kh = warp & 1;
    const int qg = lane >> 3;
    const int kg = lane & 7;
    const float* sQh = sQ + (qg * 8) * SSTR + h * HDIM;

    float lsum[8];
#pragma unroll
    for (int i = 0; i < 8; i++) lsum[i] = 0.f;

    // -------- PASS 1: denominators --------
    for (int kt = 0; kt < TT; kt += BK) {
        __syncthreads();
        for (int i = tid; i < BK * (DD / 4); i += 256) {
            const int k = i >> 5, d4 = (i & 31) * 4;
            const float4 val = *reinterpret_cast<const float4*>(gk + (size_t)(kt + k) * DD + d4);
            float* dst = sKV + k * SSTR + d4;
            dst[0] = val.x; dst[1] = val.y; dst[2] = val.z; dst[3] = val.w;
        }
        __syncthreads();

        const float* Kb = sKV + (kh * 32 + kg * 4) * SSTR + h * HDIM;
        float acc[8][4];
#pragma unroll
        for (int i = 0; i < 8; i++)
#pragma unroll
            for (int j = 0; j < 4; j++) acc[i][j] = 0.f;
#pragma unroll
        for (int d = 0; d < HDIM; d++) {
            const float b0 = Kb[d];
            const float b1 = Kb[SSTR + d];
            const float b2 = Kb[2 * SSTR + d];
            const float b3 = Kb[3 * SSTR + d];
#pragma unroll
            for (int i = 0; i < 8; i++) {
                const float a = sQh[i * SSTR + d];
                acc[i][0] += a * b0; acc[i][1] += a * b1;
                acc[i][2] += a * b2; acc[i][3] += a * b3;
            }
        }
#pragma unroll
        for (int i = 0; i < 8; i++)
            lsum[i] += __expf(acc[i][0]) + __expf(acc[i][1]) +
                       __expf(acc[i][2]) + __expf(acc[i][3]);
    }
#pragma unroll
    for (int i = 0; i < 8; i++) {
        float v = lsum[i];
        v += __shfl_down_sync(0xffffffffu, v, 4, 8);
        v += __shfl_down_sync(0xffffffffu, v, 2, 8);
        v += __shfl_down_sync(0xffffffffu, v, 1, 8);
        if (kg == 0) atomicAdd(&sL[(qg * 8 + i) * NH + h], v);
    }
    __syncthreads();
    if (tid < BQ * NH) sL[tid] = 1.0f / sL[tid];
    __syncthreads();

    float invL[8];
#pragma unroll
    for (int i = 0; i < 8; i++) invL[i] = sL[(qg * 8 + i) * NH + h];

    // ctx-phase mapping: warp -> (q-half, head); lane -> (cqg, cdg)
    const int cqh = warp >> 2, cdq = warp & 3;
    const int cqg = lane >> 3, cdg = lane & 7;
    float cacc[4][4];
#pragma unroll
    for (int i = 0; i < 4; i++)
#pragma unroll
        for (int j = 0; j < 4; j++) cacc[i][j] = 0.f;

    float* aw = attn_w + (size_t)b * TT * TT + (size_t)q0 * TT;

    // -------- PASS 2: probs + attn_w + ctx --------
    for (int kt = 0; kt < TT; kt += BK) {
        __syncthreads();
        for (int i = tid; i < BK * (DD / 4); i += 256) {
            const int k = i >> 5, d4 = (i & 31) * 4;
            const float4 val = *reinterpret_cast<const float4*>(gk + (size_t)(kt + k) * DD + d4);
            float* dst = sKV + k * SSTR + d4;
            dst[0] = val.x; dst[1] = val.y; dst[2] = val.z; dst[3] = val.w;
        }
        __syncthreads();

        const float* Kb = sKV + (kh * 32 + kg * 4) * SSTR + h * HDIM;
        float acc[8][4];
#pragma unroll
        for (int i = 0; i < 8; i++)
#pragma unroll
            for (int j = 0; j < 4; j++) acc[i][j] = 0.f;
#pragma unroll
        for (int d = 0; d < HDIM; d++) {
            const float b0 = Kb[d];
            const float b1 = Kb[SSTR + d];
            const float b2 = Kb[2 * SSTR + d];
            const float b3 = Kb[3 * SSTR + d];
#pragma unroll
            for (int i = 0; i < 8; i++) {
                const float a = sQh[i * SSTR + d];
                acc[i][0] += a * b0; acc[i][1] += a * b1;
                acc[i][2] += a * b2; acc[i][3] += a * b3;
            }
        }
        // probs into sP
        float* sPw = sP + h * BK + kh * 32 + kg * 4;
#pragma unroll
        for (int i = 0; i < 8; i++) {
            const int q = qg * 8 + i;
#pragma unroll
            for (int j = 0; j < 4; j++)
                sPw[q * PSTR + j] = __expf(acc[i][j]) * invL[i];
        }
        __syncthreads();

        // attn_w (head mean), coalesced over k
        for (int i = tid; i < BQ * BK; i += 256) {
            const int q = i >> 6, k = i & 63;
            const float* r = sP + q * PSTR + k;
            aw[(size_t)q * TT + kt + k] =
                0.25f * (r[0] + r[BK] + r[2 * BK] + r[3 * BK]);
        }
        // V tile into sKV (K no longer needed)
        for (int i = tid; i < BK * (DD / 4); i += 256) {
            const int k = i >> 5, d4 = (i & 31) * 4;
            const float4 val = *reinterpret_cast<const float4*>(gv + (size_t)(kt + k) * DD + d4);
            float* dst = sKV + k * SSTR + d4;
            dst[0] = val.x; dst[1] = val.y; dst[2] = val.z; dst[3] = val.w;
        }
        __syncthreads();

        // ctx GEMM: ctx[q][d] += P[q][cdq][k] * V[k][cdq*32 + d']
        const float* Pb = sP + (cqh * 16 + cqg * 4) * PSTR + cdq * BK;
        const float* Vb = sKV + cdq * HDIM + cdg * 4;
#pragma unroll 8
        for (int k = 0; k < BK; k++) {
            const float v0 = Vb[k * SSTR + 0];
            const float v1 = Vb[k * SSTR + 1];
            const float v2 = Vb[k * SSTR + 2];
            const float v3 = Vb[k * SSTR + 3];
#pragma unroll
            for (int i = 0; i < 4; i++) {
                const float a = Pb[i * PSTR + k];
                cacc[i][0] += a * v0; cacc[i][1] += a * v1;
                cacc[i][2] += a * v2; cacc[i][3] += a * v3;
            }
        }
    }

    float* gc = g_ctx + ((size_t)b * TT + q0 + cqh * 16 + cqg * 4) * DD + cdq * HDIM + cdg * 4;
#pragma unroll
    for (int i = 0; i < 4; i++)
#pragma unroll
        for (int j = 0; j < 4; j++)
            gc[i * DD + j] = cacc[i][j];
}

// =====================================================================
// Kernel C: out-proj + residual + LayerNorm. block = 32 tokens, 128 thr.
// =====================================================================
__global__ __launch_bounds__(128) void epilogue_kernel(
    const float* __restrict__ lob, const float* __restrict__ Wo,
    const float* __restrict__ bo, const float* __restrict__ gamma,
    const float* __restrict__ beta, float* __restrict__ out)
{
    __shared__ float sc[32][DD];
    __shared__ float sx[32][DD];

    const int t = threadIdx.x;
    const size_t tb = (size_t)blockIdx.x * 32;

    for (int i = t; i < 32 * DD; i += 128)
        sc[i >> 7][i & 127] = g_ctx[tb * DD + i];
    __syncthreads();

    float acc[32];
#pragma unroll
    for (int i = 0; i < 32; i++) acc[i] = 0.f;
    for (int jc = 0; jc < DD; jc += 16) {
        float w[16];
#pragma unroll
        for (int j = 0; j < 16; j++) w[j] = Wo[t * DD + jc + j];
#pragma unroll
        for (int tok = 0; tok < 32; tok++) {
            float a = 0.f;
#pragma unroll
            for (int j = 0; j < 16; j++) a += w[j] * sc[tok][jc + j];
            acc[tok] += a;
        }
    }
    {
        const float bov = bo[t];
#pragma unroll
        for (int tok = 0; tok < 32; tok++)
            acc[tok] += bov + lob[(tb + tok) * DD + t];
    }
    __syncthreads();
#pragma unroll
    for (int tok = 0; tok < 32; tok++) sx[tok][t] = acc[tok];
    __syncthreads();

    // LayerNorm: warp w handles 8 tokens, lane covers 4 dims
    const int warp = t >> 5, lane = t & 31;
    const float g0 = gamma[lane],      gb0 = beta[lane];
    const float g1 = gamma[lane + 32], gb1 = beta[lane + 32];
    const float g2 = gamma[lane + 64], gb2 = beta[lane + 64];
    const float g3 = gamma[lane + 96], gb3 = beta[lane + 96];

    for (int tk = 0; tk < 8; tk++) {
        const int tok = warp * 8 + tk;
        const float x0 = sx[tok][lane];
        const float x1 = sx[tok][lane + 32];
        const float x2 = sx[tok][lane + 64];
        const float x3 = sx[tok][lane + 96];
        float s = x0 + x1 + x2 + x3;
#pragma unroll
        for (int o = 16; o > 0; o >>= 1) s += __shfl_xor_sync(0xffffffffu, s, o);
        const float mu = s * (1.0f / 128.0f);
        const float d0 = x0 - mu, d1 = x1 - mu, d2 = x2 - mu, d3 = x3 - mu;
        float sq = d0 * d0 + d1 * d1 + d2 * d2 + d3 * d3;
#pragma unroll
        for (int o = 16; o > 0; o >>= 1) sq += __shfl_xor_sync(0xffffffffu, sq, o);
        const float rs = rsqrtf(sq * (1.0f / 128.0f) + 1e-5f);
        float* op = out + (tb + tok) * DD;
        op[lane]      = d0 * rs * g0 + gb0;
        op[lane + 32] = d1 * rs * g1 + gb1;
        op[lane + 64] = d2 * rs * g2 + gb2;
        op[lane + 96] = d3 * rs * g3 + gb3;
    }
}

// =====================================================================
extern "C" void kernel_launch(void* const* d_in, const int* in_sizes, int n_in,
                              void* d_out, int out_size)
{
    const float* lob    = (const float*)d_in[0];
    const float* hawkes = (const float*)d_in[1];
    const float* Wp     = (const float*)d_in[2];
    const float* bp     = (const float*)d_in[3];
    const float* Win    = (const float*)d_in[4];
    const float* bin_   = (const float*)d_in[5];
    const float* Wo     = (const float*)d_in[6];
    const float* bo     = (const float*)d_in[7];
    const float* gamma  = (const float*)d_in[8];
    const float* beta   = (const float*)d_in[9];

    float* out    = (float*)d_out;
    float* attn_w = out + (size_t)BB * TT * DD;

    const int smem_bytes = (BQ * SSTR + BK * SSTR + BQ * PSTR + BQ * NH) * sizeof(float);
    cudaFuncSetAttribute(attn_kernel, cudaFuncAttributeMaxDynamicSharedMemorySize, smem_bytes);

    qkv_kernel<<<BB * TT / 32, 128>>>(lob, hawkes, Wp, bp, Win, bin_);
    attn_kernel<<<dim3(TT / BQ, BB), 256, smem_bytes>>>(attn_w);
    epilogue_kernel<<<BB * TT / 32, 128>>>(lob, Wo, bo, gamma, beta, out);
}

// round 3
// speedup vs baseline: 1.0004x; 1.0004x over previous
#include <cuda_runtime.h>

#define BB 8
#define TT 2048
#define DD 128
#define NH 4
#define HDIM 32
#define BQ 32          // queries per attention block
#define BK 64          // keys per smem tile
#define SSTR 129       // smem row stride for Q/K/V tiles (conflict-free frags)
#define PSTR 257       // smem row stride for prob tile
#define QK_SCALE 0.17677669529663687f   // 1/sqrt(32)

// ---- scratch (static device globals; no allocation allowed) ----
__device__ float g_q[(size_t)BB*TT*DD];   // pre-scaled Q
__device__ float g_k[(size_t)BB*TT*DD];
__device__ float g_v[(size_t)BB*TT*DD];
__device__ float g_ctx[(size_t)BB*TT*DD];

// =====================================================================
// Kernel A: fused hawkes-proj + packed QKV projection.
// block = 32 tokens, 128 threads (thread t owns output dim t).
// =====================================================================
__global__ __launch_bounds__(128) void qkv_kernel(
    const float* __restrict__ lob, const float* __restrict__ hawkes,
    const float* __restrict__ Wp, const float* __restrict__ bp,
    const float* __restrict__ Win, const float* __restrict__ binv)
{
    __shared__ float sx[32][DD];    // lob tile, later overwritten with h tile
    __shared__ float shk[32][HDIM];

    const int t = threadIdx.x;
    const size_t tb = (size_t)blockIdx.x * 32;

    for (int i = t; i < 32 * DD; i += 128)
        sx[i >> 7][i & 127] = lob[tb * DD + i];
    for (int i = t; i < 32 * HDIM; i += 128)
        shk[i >> 5][i & 31] = hawkes[tb * HDIM + i];
    __syncthreads();

    // ---- q = lob @ Win[0:128].T, pre-scaled ----
    float acc[32];
#pragma unroll
    for (int i = 0; i < 32; i++) acc[i] = 0.f;
    for (int jc = 0; jc < DD; jc += 16) {
        float w[16];
#pragma unroll
        for (int j = 0; j < 16; j++) w[j] = Win[t * DD + jc + j];
#pragma unroll
        for (int tok = 0; tok < 32; tok++) {
            float a = 0.f;
#pragma unroll
            for (int j = 0; j < 16; j++) a += w[j] * sx[tok][jc + j];
            acc[tok] += a;
        }
    }
    {
        const float bq = binv[t];
#pragma unroll
        for (int tok = 0; tok < 32; tok++)
            g_q[(tb + tok) * DD + t] = (acc[tok] + bq) * QK_SCALE;
    }

    // ---- h = hawkes @ Wp.T + bp  (held in regs, then overwrite sx) ----
    float hv[32];
    {
        float w[32];
#pragma unroll
        for (int j = 0; j < 32; j++) w[j] = Wp[t * HDIM + j];
        const float bh = bp[t];
#pragma unroll
        for (int tok = 0; tok < 32; tok++) {
            float a = bh;
#pragma unroll
            for (int j = 0; j < 32; j++) a += w[j] * shk[tok][j];
            hv[tok] = a;
        }
    }
    __syncthreads();   // all q-phase reads of sx done
#pragma unroll
    for (int tok = 0; tok < 32; tok++) sx[tok][t] = hv[tok];
    __syncthreads();

    // ---- k, v from h ----
    float acck[32], accv[32];
#pragma unroll
    for (int i = 0; i < 32; i++) { acck[i] = 0.f; accv[i] = 0.f; }
    for (int jc = 0; jc < DD; jc += 16) {
        float wk[16], wv[16];
#pragma unroll
        for (int j = 0; j < 16; j++) {
            wk[j] = Win[(DD + t) * DD + jc + j];
            wv[j] = Win[(2 * DD + t) * DD + jc + j];
        }
#pragma unroll
        for (int tok = 0; tok < 32; tok++) {
            float ak = 0.f, av = 0.f;
#pragma unroll
            for (int j = 0; j < 16; j++) {
                const float x = sx[tok][jc + j];
                ak += wk[j] * x;
                av += wv[j] * x;
            }
            acck[tok] += ak;
            accv[tok] += av;
        }
    }
    {
        const float bk = binv[DD + t];
        const float bv = binv[2 * DD + t];
#pragma unroll
        for (int tok = 0; tok < 32; tok++) {
            g_k[(tb + tok) * DD + t] = acck[tok] + bk;
            g_v[(tb + tok) * DD + t] = accv[tok] + bv;
        }
    }
}

// =====================================================================
// Kernel B: attention. block = (b, 32-query tile), 256 threads.
// Pass 1: softmax denominators (no max-subtraction; |s| <~ 2).
// Pass 2: recompute scores -> probs (smem) -> attn_w write + ctx GEMM.
// =====================================================================
__global__ __launch_bounds__(256, 2) void attn_kernel(float* __restrict__ attn_w)
{
    extern __shared__ float sm[];
    float* sQ  = sm;                    // BQ  x SSTR
    float* sKV = sQ + BQ * SSTR;        // BK  x SSTR
    float* sP  = sKV + BK * SSTR;       // BQ  x PSTR   (probs: [q][h*64+k])
    float* sL  = sP + BQ * PSTR;        // BQ * NH

    const int b   = blockIdx.y;
    const int q0  = blockIdx.x * BQ;
    const int tid = threadIdx.x;
    const int warp = tid >> 5, lane = tid & 31;

    const float* gq = g_q + ((size_t)b * TT + q0) * DD;
    const float* gk = g_k + (size_t)b * TT * DD;
    const float* gv = g_v + (size_t)b * TT * DD;

    for (int i = tid; i < BQ * DD; i += 256)
        sQ[(i >> 7) * SSTR + (i & 127)] = gq[i];
    if (tid < BQ * NH) sL[tid] = 0.f;
    __syncthreads();

    // score-phase mapping: warp -> (head, key-half); lane -> (qg, kg)
    const int h  = warp >> 1;
    const int kh = warp & 1;
    const int qg = lane >> 3;
    const int kg = lane & 7;
    const float* sQh = sQ + (qg * 8) * SSTR + h * HDIM;

    float lsum[8];
#pragma unroll
    for (int i = 0; i < 8; i++) lsum[i] = 0.f;

    // -------- PASS 1: denominators --------
    for (int kt = 0; kt < TT; kt += BK) {
        __syncthreads();
        for (int i = tid; i < BK * (DD / 4); i += 256) {
            const int k = i >> 5, d4 = (i & 31) * 4;
            const float4 val = *reinterpret_cast<const float4*>(gk + (size_t)(kt + k) * DD + d4);
            float* dst = sKV + k * SSTR + d4;
            dst[0] = val.x; dst[1] = val.y; dst[2] = val.z; dst[3] = val.w;
        }
        __syncthreads();

        const float* Kb = sKV + (kh * 32 + kg * 4) * SSTR + h * HDIM;
        float acc[8][4];
#pragma unroll
        for (int i = 0; i < 8; i++)
#pragma unroll
            for (int j = 0; j < 4; j++) acc[i][j] = 0.f;
#pragma unroll
        for (int d = 0; d < HDIM; d++) {
            const float b0 = Kb[d];
            const float b1 = Kb[SSTR + d];
            const float b2 = Kb[2 * SSTR + d];
            const float b3 = Kb[3 * SSTR + d];
#pragma unroll
            for (int i = 0; i < 8; i++) {
                const float a = sQh[i * SSTR + d];
                acc[i][0] += a * b0; acc[i][1] += a * b1;
                acc[i][2] += a * b2; acc[i][3] += a * b3;
            }
        }
#pragma unroll
        for (int i = 0; i < 8; i++)
            lsum[i] += __expf(acc[i][0]) + __expf(acc[i][1]) +
                       __expf(acc[i][2]) + __expf(acc[i][3]);
    }
#pragma unroll
    for (int i = 0; i < 8; i++) {
        float v = lsum[i];
        v += __shfl_down_sync(0xffffffffu, v, 4, 8);
        v += __shfl_down_sync(0xffffffffu, v, 2, 8);
        v += __shfl_down_sync(0xffffffffu, v, 1, 8);
        if (kg == 0) atomicAdd(&sL[(qg * 8 + i) * NH + h], v);
    }
    __syncthreads();
    if (tid < BQ * NH) sL[tid] = 1.0f / sL[tid];
    __syncthreads();

    float invL[8];
#pragma unroll
    for (int i = 0; i < 8; i++) invL[i] = sL[(qg * 8 + i) * NH + h];

    // ctx-phase mapping: warp -> (q-half, head); lane -> (cqg, cdg)
    const int cqh = warp >> 2, cdq = warp & 3;
    const int cqg = lane >> 3, cdg = lane & 7;
    float cacc[4][4];
#pragma unroll
    for (int i = 0; i < 4; i++)
#pragma unroll
        for (int j = 0; j < 4; j++) cacc[i][j] = 0.f;

    float* aw = attn_w + (size_t)b * TT * TT + (size_t)q0 * TT;

    // -------- PASS 2: probs + attn_w + ctx --------
    for (int kt = 0; kt < TT; kt += BK) {
        __syncthreads();
        for (int i = tid; i < BK * (DD / 4); i += 256) {
            const int k = i >> 5, d4 = (i & 31) * 4;
            const float4 val = *reinterpret_cast<const float4*>(gk + (size_t)(kt + k) * DD + d4);
            float* dst = sKV + k * SSTR + d4;
            dst[0] = val.x; dst[1] = val.y; dst[2] = val.z; dst[3] = val.w;
        }
        __syncthreads();

        const float* Kb = sKV + (kh * 32 + kg * 4) * SSTR + h * HDIM;
        float acc[8][4];
#pragma unroll
        for (int i = 0; i < 8; i++)
#pragma unroll
            for (int j = 0; j < 4; j++) acc[i][j] = 0.f;
#pragma unroll
        for (int d = 0; d < HDIM; d++) {
            const float b0 = Kb[d];
            const float b1 = Kb[SSTR + d];
            const float b2 = Kb[2 * SSTR + d];
            const float b3 = Kb[3 * SSTR + d];
#pragma unroll
            for (int i = 0; i < 8; i++) {
                const float a = sQh[i * SSTR + d];
                acc[i][0] += a * b0; acc[i][1] += a * b1;
                acc[i][2] += a * b2; acc[i][3] += a * b3;
            }
        }
        // probs into sP
        float* sPw = sP + h * BK + kh * 32 + kg * 4;
#pragma unroll
        for (int i = 0; i < 8; i++) {
            const int q = qg * 8 + i;
#pragma unroll
            for (int j = 0; j < 4; j++)
                sPw[q * PSTR + j] = __expf(acc[i][j]) * invL[i];
        }
        __syncthreads();

        // attn_w (head mean), coalesced over k
        for (int i = tid; i < BQ * BK; i += 256) {
            const int q = i >> 6, k = i & 63;
            const float* r = sP + q * PSTR + k;
            aw[(size_t)q * TT + kt + k] =
                0.25f * (r[0] + r[BK] + r[2 * BK] + r[3 * BK]);
        }
        // V tile into sKV (K no longer needed)
        for (int i = tid; i < BK * (DD / 4); i += 256) {
            const int k = i >> 5, d4 = (i & 31) * 4;
            const float4 val = *reinterpret_cast<const float4*>(gv + (size_t)(kt + k) * DD + d4);
            float* dst = sKV + k * SSTR + d4;
            dst[0] = val.x; dst[1] = val.y; dst[2] = val.z; dst[3] = val.w;
        }
        __syncthreads();

        // ctx GEMM: ctx[q][d] += P[q][cdq][k] * V[k][cdq*32 + d']
        const float* Pb = sP + (cqh * 16 + cqg * 4) * PSTR + cdq * BK;
        const float* Vb = sKV + cdq * HDIM + cdg * 4;
#pragma unroll 8
        for (int k = 0; k < BK; k++) {
            const float v0 = Vb[k * SSTR + 0];
            const float v1 = Vb[k * SSTR + 1];
            const float v2 = Vb[k * SSTR + 2];
            const float v3 = Vb[k * SSTR + 3];
#pragma unroll
            for (int i = 0; i < 4; i++) {
                const float a = Pb[i * PSTR + k];
                cacc[i][0] += a * v0; cacc[i][1] += a * v1;
                cacc[i][2] += a * v2; cacc[i][3] += a * v3;
            }
        }
    }

    float* gc = g_ctx + ((size_t)b * TT + q0 + cqh * 16 + cqg * 4) * DD + cdq * HDIM + cdg * 4;
#pragma unroll
    for (int i = 0; i < 4; i++)
#pragma unroll
        for (int j = 0; j < 4; j++)
            gc[i * DD + j] = cacc[i][j];
}

// =====================================================================
// Kernel C: out-proj + residual + LayerNorm. block = 32 tokens, 128 thr.
// =====================================================================
__global__ __launch_bounds__(128) void epilogue_kernel(
    const float* __restrict__ lob, const float* __restrict__ Wo,
    const float* __restrict__ bo, const float* __restrict__ gamma,
    const float* __restrict__ beta, float* __restrict__ out)
{
    __shared__ float sc[32][DD];
    __shared__ float sx[32][DD];

    const int t = threadIdx.x;
    const size_t tb = (size_t)blockIdx.x * 32;

    for (int i = t; i < 32 * DD; i += 128)
        sc[i >> 7][i & 127] = g_ctx[tb * DD + i];
    __syncthreads();

    float acc[32];
#pragma unroll
    for (int i = 0; i < 32; i++) acc[i] = 0.f;
    for (int jc = 0; jc < DD; jc += 16) {
        float w[16];
#pragma unroll
        for (int j = 0; j < 16; j++) w[j] = Wo[t * DD + jc + j];
#pragma unroll
        for (int tok = 0; tok < 32; tok++) {
            float a = 0.f;
#pragma unroll
            for (int j = 0; j < 16; j++) a += w[j] * sc[tok][jc + j];
            acc[tok] += a;
        }
    }
    {
        const float bov = bo[t];
#pragma unroll
        for (int tok = 0; tok < 32; tok++)
            acc[tok] += bov + lob[(tb + tok) * DD + t];
    }
    __syncthreads();
#pragma unroll
    for (int tok = 0; tok < 32; tok++) sx[tok][t] = acc[tok];
    __syncthreads();

    // LayerNorm: warp w handles 8 tokens, lane covers 4 dims
    const int warp = t >> 5, lane = t & 31;
    const float g0 = gamma[lane],      gb0 = beta[lane];
    const float g1 = gamma[lane + 32], gb1 = beta[lane + 32];
    const float g2 = gamma[lane + 64], gb2 = beta[lane + 64];
    const float g3 = gamma[lane + 96], gb3 = beta[lane + 96];

    for (int tk = 0; tk < 8; tk++) {
        const int tok = warp * 8 + tk;
        const float x0 = sx[tok][lane];
        const float x1 = sx[tok][lane + 32];
        const float x2 = sx[tok][lane + 64];
        const float x3 = sx[tok][lane + 96];
        float s = x0 + x1 + x2 + x3;
#pragma unroll
        for (int o = 16; o > 0; o >>= 1) s += __shfl_xor_sync(0xffffffffu, s, o);
        const float mu = s * (1.0f / 128.0f);
        const float d0 = x0 - mu, d1 = x1 - mu, d2 = x2 - mu, d3 = x3 - mu;
        float sq = d0 * d0 + d1 * d1 + d2 * d2 + d3 * d3;
#pragma unroll
        for (int o = 16; o > 0; o >>= 1) sq += __shfl_xor_sync(0xffffffffu, sq, o);
        const float rs = rsqrtf(sq * (1.0f / 128.0f) + 1e-5f);
        float* op = out + (tb + tok) * DD;
        op[lane]      = d0 * rs * g0 + gb0;
        op[lane + 32] = d1 * rs * g1 + gb1;
        op[lane + 64] = d2 * rs * g2 + gb2;
        op[lane + 96] = d3 * rs * g3 + gb3;
    }
}

// =====================================================================
extern "C" void kernel_launch(void* const* d_in, const int* in_sizes, int n_in,
                              void* d_out, int out_size)
{
    const float* lob    = (const float*)d_in[0];
    const float* hawkes = (const float*)d_in[1];
    const float* Wp     = (const float*)d_in[2];
    const float* bp     = (const float*)d_in[3];
    const float* Win    = (const float*)d_in[4];
    const float* bin_   = (const float*)d_in[5];
    const float* Wo     = (const float*)d_in[6];
    const float* bo     = (const float*)d_in[7];
    const float* gamma  = (const float*)d_in[8];
    const float* beta   = (const float*)d_in[9];

    float* out    = (float*)d_out;
    float* attn_w = out + (size_t)BB * TT * DD;

    const int smem_bytes = (BQ * SSTR + BK * SSTR + BQ * PSTR + BQ * NH) * sizeof(float);
    cudaFuncSetAttribute(attn_kernel, cudaFuncAttributeMaxDynamicSharedMemorySize, smem_bytes);

    qkv_kernel<<<BB * TT / 32, 128>>>(lob, hawkes, Wp, bp, Win, bin_);
    attn_kernel<<<dim3(TT / BQ, BB), 256, smem_bytes>>>(attn_w);
    epilogue_kernel<<<BB * TT / 32, 128>>>(lob, Wo, bo, gamma, beta, out);
}